// round 6
// baseline (speedup 1.0000x reference)
#include <cuda_runtime.h>
#include <cstdint>

// Problem constants
#define B_  256
#define C_  64
#define T_  406
#define D_  10
#define TD  4060
#define MBLK 32
#define ZS1 32            // XP k-chunks (128 cols over padded 4096)
#define ZS2 4             // MQ t-chunks (128 t over padded 512)
#define ZTOT 36
#define ZCH 128
#define LDS_ 132          // padded smem row stride (conflict-free frags)

// Output offsets (floats): output_seq, input_seq, loss, indices, label, mask, proto_count
#define O_OUT  0
#define O_IN   1039360
#define O_LOSS 2078720
#define O_IDX  2095104
#define O_LAB  2095360
#define O_MASK 2095616
#define O_PC   2199552

#define N_GEMM (8 * ZTOT)            // 288
#define N_BLOCKS (N_GEMM + B_ + 1)   // 545

// smem pool layout (words): Ys 32*132=4224 | Ps 64*132=8448 | s_wn 1280
#define POOL_WORDS 13952
#define SMEM_BYTES (POOL_WORDS * 4)

// Static scratch
__device__ float g_part[ZTOT * B_ * C_];    // split-K partials (XP z<32, MQ z>=32)
__device__ float g_S1part[ZS1 * B_];
__device__ unsigned g_cnt[8];

__device__ __forceinline__ uint32_t f2tf(float f) {
    uint32_t u; asm("cvt.rna.tf32.f32 %0, %1;" : "=r"(u) : "f"(f)); return u;
}
__device__ __forceinline__ float softplus_f(float x) {
    return fmaxf(x, 0.f) + log1pf(expf(-fabsf(x)));   // jax softplus
}

// ---------------------------------------------------------------------------
// One fused kernel.
//  bid < 288:        GEMM blocks: m = bid&7 (32 b-rows), z = bid>>3.
//                    z<32: XP chunk (Y=m*wn*x on the fly vs raw proto).
//                    z>=32: MQ chunk (A=mask, B=Q computed on the fly).
//                    Every gemm block recomputes softplus-sum (identical order
//                    everywhere -> identical inv). Last-arrival per m writes loss.
//  288 <= bid < 544: copy block for sample b = bid-288 (pass-throughs, gather,
//                    indices/label).
//  bid == 544:       proto_count.
// ---------------------------------------------------------------------------
__global__ void __launch_bounds__(256) fused_kernel(
    const float* __restrict__ x, const int* __restrict__ label,
    const float* __restrict__ mask, const float* __restrict__ proto,
    const float* __restrict__ w, const float* __restrict__ pcin,
    float* __restrict__ out)
{
    extern __shared__ float s_pool[];
    __shared__ float s_red[8];
    __shared__ float s1_s[MBLK];
    __shared__ int s_cnt[C_];
    __shared__ int s_last;

    int bid = blockIdx.x, tid = threadIdx.x;

    if (bid >= N_GEMM) {
        if (bid < N_GEMM + B_) {
            // ---------------- copy block ----------------
            int b = bid - N_GEMM;
            const float4* xs = (const float4*)(x + (size_t)b * TD);
            float4* oin = (float4*)(out + O_IN + (size_t)b * TD);
            for (int i = tid; i < TD / 4; i += 256) oin[i] = xs[i];
            for (int t = tid; t < T_; t += 256)
                out[O_MASK + (size_t)b * T_ + t] = mask[(size_t)b * T_ + t];
            int lab = label[b];
            const float4* ps = (const float4*)(proto + (size_t)lab * TD);
            float4* od = (float4*)(out + O_OUT + (size_t)b * TD);
            for (int i = tid; i < TD / 4; i += 256) od[i] = ps[i];
            if (tid == 0) {
                out[O_IDX + b] = (float)lab;   // K=1 -> indices == label
                out[O_LAB + b] = (float)lab;
            }
        } else {
            // ---------------- proto_count ----------------
            if (tid < C_) s_cnt[tid] = 0;
            __syncthreads();
            atomicAdd(&s_cnt[label[tid]], 1);   // 256 threads == B_
            __syncthreads();
            if (tid < C_) out[O_PC + tid] = pcin[tid] + (float)s_cnt[tid];
        }
        return;
    }

    // ---------------- GEMM block ----------------
    int m = bid & 7, z = bid >> 3;
    int bm0 = m * MBLK;
    uint32_t (*Ys)[LDS_] = (uint32_t(*)[LDS_])s_pool;
    uint32_t (*Ps)[LDS_] = (uint32_t(*)[LDS_])(s_pool + MBLK * LDS_);
    float* s_wn = s_pool + MBLK * LDS_ + C_ * LDS_;

    int lane = tid & 31, wd = tid >> 5;

    // softplus total (redundant per block, identical reduction order everywhere)
    float ls = 0.f;
    for (int k = tid; k < TD; k += 256) ls += softplus_f(w[k]);
    for (int o = 16; o; o >>= 1) ls += __shfl_xor_sync(0xffffffffu, ls, o);
    if (lane == 0) s_red[wd] = ls;
    __syncthreads();
    float tot = 0.f;
    #pragma unroll
    for (int i = 0; i < 8; i++) tot += s_red[i];
    float inv = 1.f / tot;

    // fill s_wn for this chunk
    if (z < ZS1) {
        if (tid < ZCH) {
            int k = z * ZCH + tid;
            s_wn[tid] = (k < TD) ? softplus_f(w[k]) * inv : 0.f;
        }
    } else {
        int w0 = (z - ZS1) * ZCH * D_;
        for (int j = tid; j < ZCH * D_; j += 256) {
            int wi = w0 + j;
            s_wn[j] = (wi < TD) ? softplus_f(w[wi]) * inv : 0.f;
        }
    }
    __syncthreads();

    int row = tid >> 3, cg = tid & 7;
    if (z < ZS1) {
        // ---- XP staging: Y = m*wn*x (on the fly), P = raw proto ----
        int k0 = z * ZCH;
        int gr = bm0 + row;
        const float* xrow = x + (size_t)gr * TD;
        const float* mrow = mask + (size_t)gr * T_;
        float s1 = 0.f;
        #pragma unroll
        for (int i = 0; i < 4; i++) {
            int kc = k0 + cg * 16 + i * 4;
            float y[4] = {0.f, 0.f, 0.f, 0.f};
            if (kc < TD) {           // TD % 4 == 0 -> whole float4 valid
                float4 xv = *(const float4*)&xrow[kc];
                float xx[4] = { xv.x, xv.y, xv.z, xv.w };
                #pragma unroll
                for (int j = 0; j < 4; j++) {
                    float mm = mrow[(kc + j) / D_];
                    float yv = mm * s_wn[kc - k0 + j] * xx[j];
                    y[j] = yv;
                    s1 = fmaf(yv, xx[j], s1);
                }
            }
            uint4 u = { f2tf(y[0]), f2tf(y[1]), f2tf(y[2]), f2tf(y[3]) };
            *(uint4*)&Ys[row][cg * 16 + i * 4] = u;
        }
        // S1 partial: reduce over the 8 col-group lanes of this row
        s1 += __shfl_xor_sync(0xffffffffu, s1, 1);
        s1 += __shfl_xor_sync(0xffffffffu, s1, 2);
        s1 += __shfl_xor_sync(0xffffffffu, s1, 4);
        if (cg == 0) g_S1part[z * B_ + gr] = s1;

        #pragma unroll
        for (int uu = 0; uu < 2; uu++) {
            int u = tid + uu * 256;
            int pr = u >> 3, pc = u & 7;
            const float* prow = proto + (size_t)pr * TD;
            #pragma unroll
            for (int i = 0; i < 4; i++) {
                int kc = k0 + pc * 16 + i * 4;
                uint4 uv = {0u, 0u, 0u, 0u};
                if (kc < TD) {
                    float4 v = *(const float4*)&prow[kc];
                    uv.x = f2tf(v.x); uv.y = f2tf(v.y);
                    uv.z = f2tf(v.z); uv.w = f2tf(v.w);
                }
                *(uint4*)&Ps[pr][pc * 16 + i * 4] = uv;
            }
        }
    } else {
        // ---- MQ staging: A = mask tile, B = Q[c,t] on the fly ----
        int t0 = (z - ZS1) * ZCH;
        int gr = bm0 + row;
        #pragma unroll
        for (int i = 0; i < 4; i++) {
            int tc = t0 + cg * 16 + i * 4;
            float y[4];
            #pragma unroll
            for (int j = 0; j < 4; j++) {
                int t = tc + j;
                y[j] = (t < T_) ? mask[(size_t)gr * T_ + t] : 0.f;
            }
            uint4 u = { f2tf(y[0]), f2tf(y[1]), f2tf(y[2]), f2tf(y[3]) };
            *(uint4*)&Ys[row][cg * 16 + i * 4] = u;
        }
        #pragma unroll
        for (int uu = 0; uu < 2; uu++) {
            int u = tid + uu * 256;
            int c = u >> 3, pc = u & 7;
            #pragma unroll
            for (int i = 0; i < 4; i++) {
                float q[4];
                #pragma unroll
                for (int j = 0; j < 4; j++) {
                    int tl = pc * 16 + i * 4 + j;
                    int tg = t0 + tl;
                    float qq = 0.f;
                    if (tg < T_) {
                        const float* pp = proto + (size_t)c * TD + (size_t)tg * D_;
                        #pragma unroll
                        for (int d = 0; d < D_; d++) {
                            float pv = pp[d];
                            qq = fmaf(s_wn[tl * D_ + d] * pv, pv, qq);
                        }
                    }
                    q[j] = qq;
                }
                uint4 uv = { f2tf(q[0]), f2tf(q[1]), f2tf(q[2]), f2tf(q[3]) };
                *(uint4*)&Ps[c][pc * 16 + i * 4] = uv;
            }
        }
    }
    __syncthreads();

    // ---- tf32 MMA: 32x64 tile over 128 staged cols ----
    int wm = (wd & 1) * 16, wncol = (wd >> 1) * 16;
    int g = lane >> 2, t4 = lane & 3;
    float acc[2][4];
    #pragma unroll
    for (int nf = 0; nf < 2; nf++)
        #pragma unroll
        for (int i = 0; i < 4; i++) acc[nf][i] = 0.f;

    #pragma unroll
    for (int kk = 0; kk < ZCH; kk += 8) {
        uint32_t a0 = Ys[wm + g][kk + t4];
        uint32_t a1 = Ys[wm + g + 8][kk + t4];
        uint32_t a2 = Ys[wm + g][kk + t4 + 4];
        uint32_t a3 = Ys[wm + g + 8][kk + t4 + 4];
        #pragma unroll
        for (int nf = 0; nf < 2; nf++) {
            uint32_t b0 = Ps[wncol + nf * 8 + g][kk + t4];
            uint32_t b1 = Ps[wncol + nf * 8 + g][kk + t4 + 4];
            asm("mma.sync.aligned.m16n8k8.row.col.f32.tf32.tf32.f32 "
                "{%0,%1,%2,%3}, {%4,%5,%6,%7}, {%8,%9}, {%0,%1,%2,%3};"
                : "+f"(acc[nf][0]), "+f"(acc[nf][1]),
                  "+f"(acc[nf][2]), "+f"(acc[nf][3])
                : "r"(a0), "r"(a1), "r"(a2), "r"(a3), "r"(b0), "r"(b1));
        }
    }

    // partials
    float* part = g_part + (size_t)z * B_ * C_;
    int orow = bm0 + wm + g;
    #pragma unroll
    for (int nf = 0; nf < 2; nf++) {
        int col = wncol + nf * 8 + 2 * t4;
        *(float2*)&part[orow * C_ + col]       = make_float2(acc[nf][0], acc[nf][1]);
        *(float2*)&part[(orow + 8) * C_ + col] = make_float2(acc[nf][2], acc[nf][3]);
    }

    // last-arrival loss epilogue (atomicInc wraps -> replay-safe)
    __threadfence();
    __syncthreads();
    if (tid == 0) {
        unsigned old = atomicInc(&g_cnt[m], ZTOT - 1);
        s_last = (old == ZTOT - 1);
    }
    __syncthreads();
    if (s_last) {
        for (int r = tid; r < MBLK; r += 256) {
            float v = 0.f;
            #pragma unroll
            for (int zz = 0; zz < ZS1; zz++)
                v += __ldcg(&g_S1part[zz * B_ + bm0 + r]);
            s1_s[r] = v;
        }
        __syncthreads();
        for (int o = tid; o < MBLK * C_; o += 256) {
            int b = bm0 + (o >> 6), c = o & 63;
            float xp = 0.f, mq = 0.f;
            #pragma unroll
            for (int zz = 0; zz < ZS1; zz++)
                xp += __ldcg(&g_part[(size_t)zz * B_ * C_ + b * C_ + c]);
            #pragma unroll
            for (int zz = ZS1; zz < ZTOT; zz++)
                mq += __ldcg(&g_part[(size_t)zz * B_ * C_ + b * C_ + c]);
            out[O_LOSS + b * C_ + c] = s1_s[o >> 6] - 2.f * xp + mq;
        }
    }
}

// ---------------------------------------------------------------------------
extern "C" void kernel_launch(void* const* d_in, const int* in_sizes, int n_in,
                              void* d_out, int out_size) {
    const float* input_seq  = (const float*)d_in[0];
    const int*   label      = (const int*)  d_in[1];
    const float* mask       = (const float*)d_in[2];
    const float* prototypes = (const float*)d_in[3];
    const float* weights    = (const float*)d_in[4];
    const float* protocount = (const float*)d_in[5];
    float* out = (float*)d_out;

    cudaFuncSetAttribute(fused_kernel,
                         cudaFuncAttributeMaxDynamicSharedMemorySize, SMEM_BYTES);
    fused_kernel<<<N_BLOCKS, 256, SMEM_BYTES>>>(input_seq, label, mask,
                                                prototypes, weights,
                                                protocount, out);
}

// round 7
// speedup vs baseline: 1.0015x; 1.0015x over previous
#include <cuda_runtime.h>
#include <cstdint>

// Problem constants
#define B_  256
#define C_  64
#define T_  406
#define D_  10
#define TD  4060
#define MBLK 32
#define ZS1 32            // XP k-chunks (128 cols over padded 4096)
#define ZS2 4             // MQ t-chunks (128 t over padded 512)
#define ZTOT 36
#define ZCH 128
#define LDS_ 132          // padded smem row stride (conflict-free frags)

// Output offsets (floats): output_seq, input_seq, loss, indices, label, mask, proto_count
#define O_OUT  0
#define O_IN   1039360
#define O_LOSS 2078720
#define O_IDX  2095104
#define O_LAB  2095360
#define O_MASK 2095616
#define O_PC   2199552

#define N_GEMM (8 * ZTOT)            // 288
#define N_BLOCKS (N_GEMM + B_ + 1)   // 545

// smem pool (words): Ys 32*132=4224 | Ps 64*132=8448 | union{ [wn128|mask 32x16] , wn1280 }
#define POOL_WORDS (4224 + 8448 + 1280)
#define SMEM_BYTES (POOL_WORDS * 4)

// Static scratch
__device__ __align__(16) float g_sp[4096];   // softplus(w) (unnormalized), tail zero
__device__ float g_spsum[32];
__device__ float g_part[ZTOT * B_ * C_];     // split-K partials (XP z<32, MQ z>=32)
__device__ float g_S1part[ZS1 * B_];
__device__ unsigned g_cnt[8];

__device__ __forceinline__ uint32_t f2tf(float f) {
    uint32_t u; asm("cvt.rna.tf32.f32 %0, %1;" : "=r"(u) : "f"(f)); return u;
}

// ---------------------------------------------------------------------------
// Kernel 1: softplus spread over 32 blocks (the ONLY transcendentals).
// ---------------------------------------------------------------------------
__global__ void sp_kernel(const float* __restrict__ w) {
    __shared__ float red[4];
    int k = blockIdx.x * 128 + threadIdx.x;
    float sp = 0.f;
    if (k < TD) {
        float xv = w[k];
        sp = fmaxf(xv, 0.f) + log1pf(expf(-fabsf(xv)));   // jax softplus
        g_sp[k] = sp;
    } else {
        g_sp[k] = 0.f;
    }
    for (int o = 16; o; o >>= 1) sp += __shfl_xor_sync(0xffffffffu, sp, o);
    if ((threadIdx.x & 31) == 0) red[threadIdx.x >> 5] = sp;
    __syncthreads();
    if (threadIdx.x == 0)
        g_spsum[blockIdx.x] = red[0] + red[1] + red[2] + red[3];
}

// ---------------------------------------------------------------------------
// Kernel 2: one fused kernel.
//  bid < 288:        GEMM blocks: m = bid&7 (32 b-rows), z = bid>>3.
//                    z<32: XP chunk (Y=m*wn*x on the fly vs raw proto).
//                    z>=32: MQ chunk (A=mask, B=Q on the fly).
//  288 <= bid < 544: copy block for sample b (pass-throughs, gather, idx/label)
//  bid == 544:       proto_count.
// ---------------------------------------------------------------------------
__global__ void __launch_bounds__(256) fused_kernel(
    const float* __restrict__ x, const int* __restrict__ label,
    const float* __restrict__ mask, const float* __restrict__ proto,
    const float* __restrict__ pcin, float* __restrict__ out)
{
    extern __shared__ float s_pool[];
    __shared__ float s1_s[MBLK];
    __shared__ int s_cnt[C_];
    __shared__ int s_last;

    int bid = blockIdx.x, tid = threadIdx.x;

    if (bid >= N_GEMM) {
        if (bid < N_GEMM + B_) {
            // ---------------- copy block ----------------
            int b = bid - N_GEMM;
            const float4* xs = (const float4*)(x + (size_t)b * TD);
            float4* oin = (float4*)(out + O_IN + (size_t)b * TD);
            for (int i = tid; i < TD / 4; i += 256) oin[i] = xs[i];
            for (int t = tid; t < T_; t += 256)
                out[O_MASK + (size_t)b * T_ + t] = mask[(size_t)b * T_ + t];
            int lab = label[b];
            const float4* ps = (const float4*)(proto + (size_t)lab * TD);
            float4* od = (float4*)(out + O_OUT + (size_t)b * TD);
            for (int i = tid; i < TD / 4; i += 256) od[i] = ps[i];
            if (tid == 0) {
                out[O_IDX + b] = (float)lab;   // K=1 -> indices == label
                out[O_LAB + b] = (float)lab;
            }
        } else {
            // ---------------- proto_count ----------------
            if (tid < C_) s_cnt[tid] = 0;
            __syncthreads();
            atomicAdd(&s_cnt[label[tid]], 1);   // 256 threads == B_
            __syncthreads();
            if (tid < C_) out[O_PC + tid] = pcin[tid] + (float)s_cnt[tid];
        }
        return;
    }

    // ---------------- GEMM block ----------------
    int m = bid & 7, z = bid >> 3;
    int bm0 = m * MBLK;
    uint32_t (*Ys)[LDS_] = (uint32_t(*)[LDS_])s_pool;
    uint32_t (*Ps)[LDS_] = (uint32_t(*)[LDS_])(s_pool + MBLK * LDS_);
    float* s_wn = s_pool + MBLK * LDS_ + C_ * LDS_;
    float (*s_mask)[16] = (float(*)[16])(s_wn + 128);   // XP only (union w/ MQ wn)

    int lane = tid & 31, wd = tid >> 5;

    // total softplus sum: fixed-order sum of 32 partials (identical everywhere)
    float tot = 0.f;
    #pragma unroll
    for (int i = 0; i < 32; i++) tot += __ldg(&g_spsum[i]);
    float inv = 1.f / tot;

    int row = tid >> 3, cg = tid & 7;

    if (z < ZS1) {
        int k0 = z * ZCH;
        int t0m = k0 / D_;
        // fill s_wn chunk + mask tile
        if (tid < ZCH) s_wn[tid] = g_sp[k0 + tid] * inv;
        for (int i = tid; i < 32 * 16; i += 256) {
            int r = i >> 4, tt = i & 15;
            int tg = t0m + tt;
            s_mask[r][tt] = (tg < T_) ? mask[(size_t)(bm0 + r) * T_ + tg] : 0.f;
        }
        __syncthreads();

        // ---- XP staging: Y = m*wn*x (on the fly), P = raw proto ----
        int gr = bm0 + row;
        const float* xrow = x + (size_t)gr * TD;
        float s1 = 0.f;
        #pragma unroll
        for (int i = 0; i < 4; i++) {
            int kc = k0 + cg * 16 + i * 4;
            float y[4] = {0.f, 0.f, 0.f, 0.f};
            if (kc < TD) {               // TD % 4 == 0 -> whole float4 valid
                float4 xv = *(const float4*)&xrow[kc];
                float xx[4] = { xv.x, xv.y, xv.z, xv.w };
                #pragma unroll
                for (int j = 0; j < 4; j++) {
                    float mm = s_mask[row][(kc + j) / D_ - t0m];
                    float yv = mm * s_wn[kc - k0 + j] * xx[j];
                    y[j] = yv;
                    s1 = fmaf(yv, xx[j], s1);
                }
            }
            uint4 u = { f2tf(y[0]), f2tf(y[1]), f2tf(y[2]), f2tf(y[3]) };
            *(uint4*)&Ys[row][cg * 16 + i * 4] = u;
        }
        // S1 partial: reduce over the 8 col-group lanes of this row
        s1 += __shfl_xor_sync(0xffffffffu, s1, 1);
        s1 += __shfl_xor_sync(0xffffffffu, s1, 2);
        s1 += __shfl_xor_sync(0xffffffffu, s1, 4);
        if (cg == 0) g_S1part[z * B_ + gr] = s1;

        #pragma unroll
        for (int uu = 0; uu < 2; uu++) {
            int u = tid + uu * 256;
            int pr = u >> 3, pc = u & 7;
            const float* prow = proto + (size_t)pr * TD;
            #pragma unroll
            for (int i = 0; i < 4; i++) {
                int kc = k0 + pc * 16 + i * 4;
                uint4 uv = {0u, 0u, 0u, 0u};
                if (kc < TD) {
                    float4 v = *(const float4*)&prow[kc];
                    uv.x = f2tf(v.x); uv.y = f2tf(v.y);
                    uv.z = f2tf(v.z); uv.w = f2tf(v.w);
                }
                *(uint4*)&Ps[pr][pc * 16 + i * 4] = uv;
            }
        }
    } else {
        int t0 = (z - ZS1) * ZCH;
        int w0 = t0 * D_;
        for (int j = tid; j < ZCH * D_; j += 256) {
            int wi = w0 + j;
            s_wn[j] = (wi < TD) ? g_sp[wi] * inv : 0.f;
        }
        __syncthreads();

        // ---- MQ staging: A = mask tile, B = Q[c,t] on the fly ----
        int gr = bm0 + row;
        #pragma unroll
        for (int i = 0; i < 4; i++) {
            int tc = t0 + cg * 16 + i * 4;
            float y[4];
            #pragma unroll
            for (int j = 0; j < 4; j++) {
                int t = tc + j;
                y[j] = (t < T_) ? mask[(size_t)gr * T_ + t] : 0.f;
            }
            uint4 u = { f2tf(y[0]), f2tf(y[1]), f2tf(y[2]), f2tf(y[3]) };
            *(uint4*)&Ys[row][cg * 16 + i * 4] = u;
        }
        #pragma unroll
        for (int uu = 0; uu < 2; uu++) {
            int u = tid + uu * 256;
            int c = u >> 3, pc = u & 7;
            #pragma unroll
            for (int i = 0; i < 4; i++) {
                float q[4];
                #pragma unroll
                for (int j = 0; j < 4; j++) {
                    int tl = pc * 16 + i * 4 + j;
                    int tg = t0 + tl;
                    float qq = 0.f;
                    if (tg < T_) {
                        const float* pp = proto + (size_t)c * TD + (size_t)tg * D_;
                        #pragma unroll
                        for (int d = 0; d < D_; d++) {
                            float pv = pp[d];
                            qq = fmaf(s_wn[tl * D_ + d] * pv, pv, qq);
                        }
                    }
                    q[j] = qq;
                }
                uint4 uv = { f2tf(q[0]), f2tf(q[1]), f2tf(q[2]), f2tf(q[3]) };
                *(uint4*)&Ps[c][pc * 16 + i * 4] = uv;
            }
        }
    }
    __syncthreads();

    // ---- tf32 MMA: 32x64 tile over 128 staged cols ----
    int wm = (wd & 1) * 16, wncol = (wd >> 1) * 16;
    int g = lane >> 2, t4 = lane & 3;
    float acc[2][4];
    #pragma unroll
    for (int nf = 0; nf < 2; nf++)
        #pragma unroll
        for (int i = 0; i < 4; i++) acc[nf][i] = 0.f;

    #pragma unroll
    for (int kk = 0; kk < ZCH; kk += 8) {
        uint32_t a0 = Ys[wm + g][kk + t4];
        uint32_t a1 = Ys[wm + g + 8][kk + t4];
        uint32_t a2 = Ys[wm + g][kk + t4 + 4];
        uint32_t a3 = Ys[wm + g + 8][kk + t4 + 4];
        #pragma unroll
        for (int nf = 0; nf < 2; nf++) {
            uint32_t b0 = Ps[wncol + nf * 8 + g][kk + t4];
            uint32_t b1 = Ps[wncol + nf * 8 + g][kk + t4 + 4];
            asm("mma.sync.aligned.m16n8k8.row.col.f32.tf32.tf32.f32 "
                "{%0,%1,%2,%3}, {%4,%5,%6,%7}, {%8,%9}, {%0,%1,%2,%3};"
                : "+f"(acc[nf][0]), "+f"(acc[nf][1]),
                  "+f"(acc[nf][2]), "+f"(acc[nf][3])
                : "r"(a0), "r"(a1), "r"(a2), "r"(a3), "r"(b0), "r"(b1));
        }
    }

    // partials
    float* part = g_part + (size_t)z * B_ * C_;
    int orow = bm0 + wm + g;
    #pragma unroll
    for (int nf = 0; nf < 2; nf++) {
        int col = wncol + nf * 8 + 2 * t4;
        *(float2*)&part[orow * C_ + col]       = make_float2(acc[nf][0], acc[nf][1]);
        *(float2*)&part[(orow + 8) * C_ + col] = make_float2(acc[nf][2], acc[nf][3]);
    }

    // last-arrival loss epilogue (atomicInc wraps -> replay-safe)
    __threadfence();
    __syncthreads();
    if (tid == 0) {
        unsigned old = atomicInc(&g_cnt[m], ZTOT - 1);
        s_last = (old == ZTOT - 1);
    }
    __syncthreads();
    if (s_last) {
        for (int r = tid; r < MBLK; r += 256) {
            float v = 0.f;
            #pragma unroll
            for (int zz = 0; zz < ZS1; zz++)
                v += __ldcg(&g_S1part[zz * B_ + bm0 + r]);
            s1_s[r] = v;
        }
        __syncthreads();
        for (int o = tid; o < MBLK * C_; o += 256) {
            int b = bm0 + (o >> 6), c = o & 63;
            float xp = 0.f, mq = 0.f;
            #pragma unroll
            for (int zz = 0; zz < ZS1; zz++)
                xp += __ldcg(&g_part[(size_t)zz * B_ * C_ + b * C_ + c]);
            #pragma unroll
            for (int zz = ZS1; zz < ZTOT; zz++)
                mq += __ldcg(&g_part[(size_t)zz * B_ * C_ + b * C_ + c]);
            out[O_LOSS + b * C_ + c] = s1_s[o >> 6] - 2.f * xp + mq;
        }
    }
}

// ---------------------------------------------------------------------------
extern "C" void kernel_launch(void* const* d_in, const int* in_sizes, int n_in,
                              void* d_out, int out_size) {
    const float* input_seq  = (const float*)d_in[0];
    const int*   label      = (const int*)  d_in[1];
    const float* mask       = (const float*)d_in[2];
    const float* prototypes = (const float*)d_in[3];
    const float* weights    = (const float*)d_in[4];
    const float* protocount = (const float*)d_in[5];
    float* out = (float*)d_out;

    sp_kernel<<<32, 128>>>(weights);
    cudaFuncSetAttribute(fused_kernel,
                         cudaFuncAttributeMaxDynamicSharedMemorySize, SMEM_BYTES);
    fused_kernel<<<N_BLOCKS, 256, SMEM_BYTES>>>(input_seq, label, mask,
                                                prototypes, protocount, out);
}

// round 8
// speedup vs baseline: 2.1621x; 2.1589x over previous
#include <cuda_runtime.h>
#include <cstdint>

// Problem constants
#define B_  256
#define C_  64
#define T_  406
#define D_  10
#define TD  4060
#define KP  4608          // [0,4060)=m*wn*x | [4060,4466)=mask | rest 0
#define MBLK 32
#define ZTOT 36           // KP / 128
#define ZCH 128
#define LDS_ 132          // padded smem row stride (conflict-free frags)

// Output offsets (floats): output_seq, input_seq, loss, indices, label, mask, proto_count
#define O_OUT  0
#define O_IN   1039360
#define O_LOSS 2078720
#define O_IDX  2095104
#define O_LAB  2095360
#define O_MASK 2095616
#define O_PC   2199552

#define N_GEMM (8 * ZTOT)            // 288
#define N_BLOCKS (N_GEMM + B_ + 1)   // 545

// main-kernel smem pool (words): Ys 32*132 | Ps 64*132 | wn 128
#define POOL_WORDS (4224 + 8448 + 128)
#define SMEM_BYTES (POOL_WORDS * 4)

// Static scratch
__device__ __align__(16) float g_sp[4096];   // softplus(w), tail zero
__device__ float g_spsum[32];
__device__ __align__(16) float g_P[C_ * KP]; // 1.18 MB  P' rows
__device__ float g_part[ZTOT * B_ * C_];     // split-K partials
__device__ float g_S1part[ZTOT * B_];
__device__ unsigned g_cnt[8];

__device__ __forceinline__ uint32_t f2tf(float f) {
    uint32_t u; asm("cvt.rna.tf32.f32 %0, %1;" : "=r"(u) : "f"(f)); return u;
}

// ---------------------------------------------------------------------------
// Kernel 1: softplus over 32 blocks (the ONLY transcendentals).
// ---------------------------------------------------------------------------
__global__ void sp_kernel(const float* __restrict__ w) {
    __shared__ float red[4];
    int k = blockIdx.x * 128 + threadIdx.x;
    float sp = 0.f;
    if (k < TD) {
        float xv = w[k];
        sp = fmaxf(xv, 0.f) + log1pf(expf(-fabsf(xv)));   // jax softplus
        g_sp[k] = sp;
    } else {
        g_sp[k] = 0.f;
    }
    for (int o = 16; o; o >>= 1) sp += __shfl_xor_sync(0xffffffffu, sp, o);
    if ((threadIdx.x & 31) == 0) red[threadIdx.x >> 5] = sp;
    __syncthreads();
    if (threadIdx.x == 0)
        g_spsum[blockIdx.x] = red[0] + red[1] + red[2] + red[3];
}

// ---------------------------------------------------------------------------
// Kernel 2: build P' row c = [p | -0.5*inv*Q | 0], proto staged via smem.
// grid = 64 blocks.
// ---------------------------------------------------------------------------
__global__ void __launch_bounds__(256) prepP_kernel(const float* __restrict__ proto) {
    __shared__ __align__(16) float s_p[TD];
    int c = blockIdx.x, tid = threadIdx.x;

    float tot = 0.f;
    #pragma unroll
    for (int i = 0; i < 32; i++) tot += __ldg(&g_spsum[i]);
    float inv = 1.f / tot;

    const float4* src = (const float4*)(proto + (size_t)c * TD);
    float4* Pd = (float4*)(g_P + (size_t)c * KP);
    float4* sp4 = (float4*)s_p;
    for (int i = tid; i < TD / 4; i += 256) {
        float4 v = src[i];
        sp4[i] = v;
        Pd[i] = v;                       // copy p into P' head
    }
    __syncthreads();
    float* Pr = g_P + (size_t)c * KP;
    for (int t = tid; t < T_; t += 256) {
        float q = 0.f;
        #pragma unroll
        for (int d = 0; d < D_; d++) {
            float pv = s_p[t * D_ + d];
            q = fmaf(g_sp[t * D_ + d] * pv, pv, q);
        }
        Pr[TD + t] = -0.5f * inv * q;
    }
    for (int k = TD + T_ + tid; k < KP; k += 256) Pr[k] = 0.f;
}

// ---------------------------------------------------------------------------
// Kernel 3: main. bid<288: gemm (m=bid&7, z=bid>>3) over virtual-K columns,
// Y on the fly; 288..543: copy block; 544: proto_count.
// Last-arrival block per m writes loss = S1 - 2*dot.
// ---------------------------------------------------------------------------
__global__ void __launch_bounds__(256) main_kernel(
    const float* __restrict__ x, const int* __restrict__ label,
    const float* __restrict__ mask, const float* __restrict__ proto,
    const float* __restrict__ pcin, float* __restrict__ out)
{
    extern __shared__ float s_pool[];
    __shared__ float s1_s[MBLK];
    __shared__ int s_cnt[C_];
    __shared__ int s_last;

    int bid = blockIdx.x, tid = threadIdx.x;

    if (bid >= N_GEMM) {
        if (bid < N_GEMM + B_) {
            // ---------------- copy block ----------------
            int b = bid - N_GEMM;
            const float4* xs = (const float4*)(x + (size_t)b * TD);
            float4* oin = (float4*)(out + O_IN + (size_t)b * TD);
            for (int i = tid; i < TD / 4; i += 256) oin[i] = xs[i];
            for (int t = tid; t < T_; t += 256)
                out[O_MASK + (size_t)b * T_ + t] = mask[(size_t)b * T_ + t];
            int lab = label[b];
            const float4* ps = (const float4*)(proto + (size_t)lab * TD);
            float4* od = (float4*)(out + O_OUT + (size_t)b * TD);
            for (int i = tid; i < TD / 4; i += 256) od[i] = ps[i];
            if (tid == 0) {
                out[O_IDX + b] = (float)lab;   // K=1 -> indices == label
                out[O_LAB + b] = (float)lab;
            }
        } else {
            // ---------------- proto_count ----------------
            if (tid < C_) s_cnt[tid] = 0;
            __syncthreads();
            atomicAdd(&s_cnt[label[tid]], 1);   // 256 threads == B_
            __syncthreads();
            if (tid < C_) out[O_PC + tid] = pcin[tid] + (float)s_cnt[tid];
        }
        return;
    }

    // ---------------- GEMM block ----------------
    int m = bid & 7, z = bid >> 3;
    int bm0 = m * MBLK;
    int k0 = z * ZCH;
    uint32_t (*Ys)[LDS_] = (uint32_t(*)[LDS_])s_pool;
    uint32_t (*Ps)[LDS_] = (uint32_t(*)[LDS_])(s_pool + MBLK * LDS_);
    float* s_wn = s_pool + MBLK * LDS_ + C_ * LDS_;

    int lane = tid & 31, wd = tid >> 5;

    float tot = 0.f;
    #pragma unroll
    for (int i = 0; i < 32; i++) tot += __ldg(&g_spsum[i]);
    float inv = 1.f / tot;

    if (tid < ZCH) {
        int k = k0 + tid;
        s_wn[tid] = (k < 4096) ? g_sp[k] * inv : 0.f;   // g_sp tail is zero
    }
    __syncthreads();

    // ---- Y staging: [m*wn*x | mask | 0], S1 partial ----
    int row = tid >> 3, cg = tid & 7;
    int gr = bm0 + row;
    const float* xrow = x + (size_t)gr * TD;
    const float* mrow = mask + (size_t)gr * T_;
    float s1 = 0.f;
    #pragma unroll
    for (int i = 0; i < 4; i++) {
        int kc = k0 + cg * 16 + i * 4;                  // kc % 4 == 0
        float y[4] = {0.f, 0.f, 0.f, 0.f};
        if (kc < TD) {                                  // TD % 4 == 0: whole float4
            float4 xv = *(const float4*)&xrow[kc];
            float xx[4] = { xv.x, xv.y, xv.z, xv.w };
            #pragma unroll
            for (int j = 0; j < 4; j++) {
                float mm = __ldg(&mrow[(kc + j) / D_]);
                float yv = mm * s_wn[kc - k0 + j] * xx[j];
                y[j] = yv;
                s1 = fmaf(yv, xx[j], s1);
            }
        } else {
            #pragma unroll
            for (int j = 0; j < 4; j++) {
                int k = kc + j;
                y[j] = (k < TD + T_) ? __ldg(&mrow[k - TD]) : 0.f;
            }
        }
        uint4 u = { f2tf(y[0]), f2tf(y[1]), f2tf(y[2]), f2tf(y[3]) };
        *(uint4*)&Ys[row][cg * 16 + i * 4] = u;
    }
    // S1 partial: reduce over the 8 col-groups of this row (deterministic)
    s1 += __shfl_xor_sync(0xffffffffu, s1, 1);
    s1 += __shfl_xor_sync(0xffffffffu, s1, 2);
    s1 += __shfl_xor_sync(0xffffffffu, s1, 4);
    if (cg == 0) g_S1part[z * B_ + gr] = s1;

    // ---- P staging from g_P (coalesced float4) ----
    #pragma unroll
    for (int uu = 0; uu < 2; uu++) {
        int u = tid + uu * 256;
        int pr = u >> 3, pc = u & 7;
        const float* prow = g_P + (size_t)pr * KP + k0;
        #pragma unroll
        for (int i = 0; i < 4; i++) {
            float4 v = *(const float4*)&prow[pc * 16 + i * 4];
            uint4 uv = { f2tf(v.x), f2tf(v.y), f2tf(v.z), f2tf(v.w) };
            *(uint4*)&Ps[pr][pc * 16 + i * 4] = uv;
        }
    }
    __syncthreads();

    // ---- tf32 MMA: 32x64 tile over 128 staged cols ----
    int wm = (wd & 1) * 16, wncol = (wd >> 1) * 16;
    int g = lane >> 2, t4 = lane & 3;
    float acc[2][4];
    #pragma unroll
    for (int nf = 0; nf < 2; nf++)
        #pragma unroll
        for (int i = 0; i < 4; i++) acc[nf][i] = 0.f;

    #pragma unroll
    for (int kk = 0; kk < ZCH; kk += 8) {
        uint32_t a0 = Ys[wm + g][kk + t4];
        uint32_t a1 = Ys[wm + g + 8][kk + t4];
        uint32_t a2 = Ys[wm + g][kk + t4 + 4];
        uint32_t a3 = Ys[wm + g + 8][kk + t4 + 4];
        #pragma unroll
        for (int nf = 0; nf < 2; nf++) {
            uint32_t b0 = Ps[wncol + nf * 8 + g][kk + t4];
            uint32_t b1 = Ps[wncol + nf * 8 + g][kk + t4 + 4];
            asm("mma.sync.aligned.m16n8k8.row.col.f32.tf32.tf32.f32 "
                "{%0,%1,%2,%3}, {%4,%5,%6,%7}, {%8,%9}, {%0,%1,%2,%3};"
                : "+f"(acc[nf][0]), "+f"(acc[nf][1]),
                  "+f"(acc[nf][2]), "+f"(acc[nf][3])
                : "r"(a0), "r"(a1), "r"(a2), "r"(a3), "r"(b0), "r"(b1));
        }
    }

    // partials
    float* part = g_part + (size_t)z * B_ * C_;
    int orow = bm0 + wm + g;
    #pragma unroll
    for (int nf = 0; nf < 2; nf++) {
        int col = wncol + nf * 8 + 2 * t4;
        *(float2*)&part[orow * C_ + col]       = make_float2(acc[nf][0], acc[nf][1]);
        *(float2*)&part[(orow + 8) * C_ + col] = make_float2(acc[nf][2], acc[nf][3]);
    }

    // last-arrival loss epilogue (atomicInc wraps -> replay-safe)
    __threadfence();
    __syncthreads();
    if (tid == 0) {
        unsigned old = atomicInc(&g_cnt[m], ZTOT - 1);
        s_last = (old == ZTOT - 1);
    }
    __syncthreads();
    if (s_last) {
        for (int r = tid; r < MBLK; r += 256) {
            float v = 0.f;
            #pragma unroll
            for (int zz = 0; zz < ZTOT; zz++)
                v += __ldcg(&g_S1part[zz * B_ + bm0 + r]);
            s1_s[r] = v;
        }
        __syncthreads();
        for (int o = tid; o < MBLK * C_; o += 256) {
            int b = bm0 + (o >> 6), c = o & 63;
            float s = 0.f;
            #pragma unroll
            for (int zz = 0; zz < ZTOT; zz++)
                s += __ldcg(&g_part[(size_t)zz * B_ * C_ + b * C_ + c]);
            out[O_LOSS + b * C_ + c] = s1_s[o >> 6] - 2.f * s;
        }
    }
}

// ---------------------------------------------------------------------------
extern "C" void kernel_launch(void* const* d_in, const int* in_sizes, int n_in,
                              void* d_out, int out_size) {
    const float* input_seq  = (const float*)d_in[0];
    const int*   label      = (const int*)  d_in[1];
    const float* mask       = (const float*)d_in[2];
    const float* prototypes = (const float*)d_in[3];
    const float* weights    = (const float*)d_in[4];
    const float* protocount = (const float*)d_in[5];
    float* out = (float*)d_out;

    sp_kernel<<<32, 128>>>(weights);
    prepP_kernel<<<C_, 256>>>(prototypes);
    cudaFuncSetAttribute(main_kernel,
                         cudaFuncAttributeMaxDynamicSharedMemorySize, SMEM_BYTES);
    main_kernel<<<N_BLOCKS, 256, SMEM_BYTES>>>(input_seq, label, mask,
                                               prototypes, protocount, out);
}